// round 2
// baseline (speedup 1.0000x reference)
#include <cuda_runtime.h>
#include <cuda_bf16.h>

#define N_ATOMS 100000
#define N_PAIRS 6400000
#define LOG2E 1.4426950408889634f

struct ZParams {
    float cbase;            // softmax coeff of the min-exponent term
    float ca, cb, cc;       // softmax coeffs of the other three terms
    float ga, gb, gc;       // -(e_k - e_min)*log2(e)/|a_coef|
};
__device__ ZParams g_params;
__device__ float2 g_tbl_i[N_ATOMS];   // {Z*atom_mask, Z^|a_exp|}
__device__ float2 g_tbl_j[N_ATOMS];   // {Z,           Z^|a_exp|}

__device__ __forceinline__ float ex2a(float x) {
    float r; asm("ex2.approx.f32 %0, %1;" : "=f"(r) : "f"(x)); return r;
}
__device__ __forceinline__ float lg2a(float x) {
    float r; asm("lg2.approx.f32 %0, %1;" : "=f"(r) : "f"(x)); return r;
}
__device__ __forceinline__ float rsqa(float x) {
    float r; asm("rsqrt.approx.f32 %0, %1;" : "=f"(r) : "f"(x)); return r;
}

__global__ void prep_kernel(const float* __restrict__ Z,
                            const float* __restrict__ amask,
                            const float* __restrict__ a_coef,
                            const float* __restrict__ a_exp,
                            const float* __restrict__ pc,
                            const float* __restrict__ pe,
                            float* __restrict__ out)
{
    int tid = blockIdx.x * blockDim.x + threadIdx.x;
    float aexp = fabsf(a_exp[0]);
    for (int i = tid; i < N_ATOMS; i += gridDim.x * blockDim.x) {
        float z = Z[i];
        float za = ex2a(aexp * lg2a(z));   // z^aexp, z in [1,94] > 0
        g_tbl_i[i] = make_float2(z * amask[i], za);
        g_tbl_j[i] = make_float2(z, za);
        out[i] = 0.0f;
    }
    if (tid == 0) {
        float c[4], e[4];
        float m = -1e30f;
        #pragma unroll
        for (int k = 0; k < 4; k++) {
            c[k] = fabsf(pc[k]);
            e[k] = fabsf(pe[k]);
            if (c[k] > m) m = c[k];
        }
        float sum = 0.0f, w[4];
        #pragma unroll
        for (int k = 0; k < 4; k++) { w[k] = expf(c[k] - m); sum += w[k]; }
        #pragma unroll
        for (int k = 0; k < 4; k++) w[k] /= sum;
        int kmin = 0;
        #pragma unroll
        for (int k = 1; k < 4; k++) if (e[k] < e[kmin]) kmin = k;
        float acoef = fabsf(a_coef[0]);
        float scale = -LOG2E / acoef;
        ZParams p;
        p.cbase = w[kmin];
        float* cs = &p.ca;
        float* gs = &p.ga;
        int n = 0;
        for (int k = 0; k < 4; k++) {
            if (k == kmin) continue;
            cs[n] = w[k];
            gs[n] = (e[k] - e[kmin]) * scale;
            n++;
        }
        g_params = p;
    }
}

#define PPT 8           // pairs per thread
#define TPB 256

__global__ void __launch_bounds__(TPB) pair_kernel(
    const float4* __restrict__ disp4,
    const int4*   __restrict__ ii4,
    const int4*   __restrict__ jj4,
    const float4* __restrict__ bm4,
    float*        __restrict__ out)
{
    int t = blockIdx.x * blockDim.x + threadIdx.x;
    if (t >= N_PAIRS / PPT) return;

    // ---- front-batched streaming loads (max MLP) ----
    float4 dv[PPT * 3 / 4];
    #pragma unroll
    for (int q = 0; q < PPT * 3 / 4; q++) dv[q] = disp4[(PPT * 3 / 4) * t + q];

    int4 iiA = ii4[2 * t + 0], iiB = ii4[2 * t + 1];
    int4 jjA = jj4[2 * t + 0], jjB = jj4[2 * t + 1];
    float4 bmA = bm4[2 * t + 0], bmB = bm4[2 * t + 1];

    int ks[PPT] = {iiA.x, iiA.y, iiA.z, iiA.w, iiB.x, iiB.y, iiB.z, iiB.w};
    int js[PPT] = {jjA.x, jjA.y, jjA.z, jjA.w, jjB.x, jjB.y, jjB.z, jjB.w};
    float bs[PPT] = {bmA.x, bmA.y, bmA.z, bmA.w, bmB.x, bmB.y, bmB.z, bmB.w};

    // ---- unconditional gathers, issued before any dependent math ----
    float2 ti[PPT], tj[PPT];
    #pragma unroll
    for (int m = 0; m < PPT; m++) {
        ti[m] = g_tbl_i[ks[m]];
        tj[m] = g_tbl_j[js[m]];
    }

    ZParams p = g_params;
    const float* buf = (const float*)dv;

    float vs[PPT];
    #pragma unroll
    for (int m = 0; m < PPT; m++) {
        float x = buf[3 * m + 0], y = buf[3 * m + 1], z = buf[3 * m + 2];
        float r2 = fmaf(x, x, fmaf(y, y, z * z));
        r2 = fmaxf(r2, 1e-20f);
        float rinv = rsqa(r2);
        float d = r2 * rinv;               // d = sqrt(r2), rinv = 1/d

        float s  = fmaxf(ti[m].y + tj[m].y, 1e-10f);
        float ds = d * s;
        float ea = ex2a(p.ga * ds);
        float eb = ex2a(p.gb * ds);
        float ec = ex2a(p.gc * ds);
        float phi = fmaf(p.ca, ea, fmaf(p.cb, eb, fmaf(p.cc, ec, p.cbase)));

        float xq = 5.0f - d;
        float poly = fmaf(fmaf(6.0f, xq, -15.0f), xq, 10.0f) * (xq * xq * xq);
        float sw = (d < 4.0f) ? 1.0f : ((d < 5.0f) ? poly : 0.0f);

        vs[m] = 0.5f * ti[m].x * tj[m].x * phi * sw * bs[m] * rinv;
    }

    // ---- thread-local merge over sorted keys, flush runs via atomicAdd ----
    float acc = vs[0];
    int   key = ks[0];
    #pragma unroll
    for (int m = 1; m < PPT; m++) {
        if (ks[m] == key) {
            acc += vs[m];
        } else {
            if (acc != 0.0f) atomicAdd(&out[key], acc);
            key = ks[m];
            acc = vs[m];
        }
    }
    if (acc != 0.0f) atomicAdd(&out[key], acc);
}

extern "C" void kernel_launch(void* const* d_in, const int* in_sizes, int n_in,
                              void* d_out, int out_size)
{
    const float* Z     = (const float*)d_in[0];
    const float* disp  = (const float*)d_in[1];
    const int*   idx_i = (const int*)d_in[2];
    const int*   idx_j = (const int*)d_in[3];
    const float* amask = (const float*)d_in[4];
    const float* bmask = (const float*)d_in[6];
    const float* acoef = (const float*)d_in[n_in - 4];
    const float* aexp  = (const float*)d_in[n_in - 3];
    const float* pc    = (const float*)d_in[n_in - 2];
    const float* pe    = (const float*)d_in[n_in - 1];
    float* out = (float*)d_out;

    (void)in_sizes; (void)out_size;

    prep_kernel<<<800, 128>>>(Z, amask, acoef, aexp, pc, pe, out);

    int nthreads = N_PAIRS / PPT;
    pair_kernel<<<(nthreads + TPB - 1) / TPB, TPB>>>(
        (const float4*)disp, (const int4*)idx_i, (const int4*)idx_j,
        (const float4*)bmask, out);
}

// round 4
// speedup vs baseline: 1.1412x; 1.1412x over previous
#include <cuda_runtime.h>
#include <cuda_bf16.h>

#define N_ATOMS 100000
#define N_PAIRS 6400000
#define LOG2E 1.4426950408889634f

struct ZParams {
    float cbase;            // softmax coeff of the min-exponent term
    float ca, cb, cc;       // softmax coeffs of the other three terms
    float ga, gb, gc;       // -(e_k - e_min)*log2(e)/|a_coef|
};
__device__ ZParams g_params;
__device__ float2 g_tbl_i[N_ATOMS];   // {Z*atom_mask, Z^|a_exp|}
__device__ float2 g_tbl_j[N_ATOMS];   // {Z,           Z^|a_exp|}

__device__ __forceinline__ float ex2a(float x) {
    float r; asm("ex2.approx.f32 %0, %1;" : "=f"(r) : "f"(x)); return r;
}
__device__ __forceinline__ float lg2a(float x) {
    float r; asm("lg2.approx.f32 %0, %1;" : "=f"(r) : "f"(x)); return r;
}
__device__ __forceinline__ float rsqa(float x) {
    float r; asm("rsqrt.approx.f32 %0, %1;" : "=f"(r) : "f"(x)); return r;
}

__global__ void prep_kernel(const float* __restrict__ Z,
                            const float* __restrict__ amask,
                            const float* __restrict__ a_coef,
                            const float* __restrict__ a_exp,
                            const float* __restrict__ pc,
                            const float* __restrict__ pe,
                            float* __restrict__ out)
{
    int tid = blockIdx.x * blockDim.x + threadIdx.x;
    float aexp = fabsf(a_exp[0]);
    for (int i = tid; i < N_ATOMS; i += gridDim.x * blockDim.x) {
        float z = Z[i];
        float za = ex2a(aexp * lg2a(z));   // z^aexp, z in [1,94] > 0
        g_tbl_i[i] = make_float2(z * amask[i], za);
        g_tbl_j[i] = make_float2(z, za);
        out[i] = 0.0f;
    }
    if (tid == 0) {
        float c[4], e[4];
        float m = -1e30f;
        #pragma unroll
        for (int k = 0; k < 4; k++) {
            c[k] = fabsf(pc[k]);
            e[k] = fabsf(pe[k]);
            if (c[k] > m) m = c[k];
        }
        float sum = 0.0f, w[4];
        #pragma unroll
        for (int k = 0; k < 4; k++) { w[k] = expf(c[k] - m); sum += w[k]; }
        #pragma unroll
        for (int k = 0; k < 4; k++) w[k] /= sum;
        int kmin = 0;
        #pragma unroll
        for (int k = 1; k < 4; k++) if (e[k] < e[kmin]) kmin = k;
        float acoef = fabsf(a_coef[0]);
        float scale = -LOG2E / acoef;
        ZParams p;
        p.cbase = w[kmin];
        float* cs = &p.ca;
        float* gs = &p.ga;
        int n = 0;
        for (int k = 0; k < 4; k++) {
            if (k == kmin) continue;
            cs[n] = w[k];
            gs[n] = (e[k] - e[kmin]) * scale;
            n++;
        }
        g_params = p;
    }
}

#define PPT 4
#define TPB 256

__global__ void __launch_bounds__(TPB, 6) pair_kernel(
    const float4* __restrict__ disp4,
    const int4*   __restrict__ ii4,
    const int4*   __restrict__ jj4,
    const float4* __restrict__ bm4,
    float*        __restrict__ out)
{
    const int t = blockIdx.x * TPB + threadIdx.x;   // grid sized exactly
    const unsigned lane = threadIdx.x & 31u;

    // ---- streaming loads: evict-first so L1 keeps the gather tables ----
    float4 d0 = __ldcs(disp4 + 3 * t + 0);
    float4 d1 = __ldcs(disp4 + 3 * t + 1);
    float4 d2 = __ldcs(disp4 + 3 * t + 2);
    int4   ii = __ldcs(ii4 + t);
    int4   jj = __ldcs(jj4 + t);
    float4 bm = __ldcs(bm4 + t);

    int   ks[PPT] = {ii.x, ii.y, ii.z, ii.w};
    int   js[PPT] = {jj.x, jj.y, jj.z, jj.w};
    float bs[PPT] = {bm.x, bm.y, bm.z, bm.w};

    // ---- unconditional gathers, issued before dependent math ----
    float2 ti[PPT], tj[PPT];
    #pragma unroll
    for (int m = 0; m < PPT; m++) {
        ti[m] = g_tbl_i[ks[m]];
        tj[m] = g_tbl_j[js[m]];
    }

    ZParams p = g_params;

    float xs[PPT] = {d0.x, d0.w, d1.z, d2.y};
    float ys[PPT] = {d0.y, d1.x, d1.w, d2.z};
    float zs[PPT] = {d0.z, d1.y, d2.x, d2.w};

    float vs[PPT];
    #pragma unroll
    for (int m = 0; m < PPT; m++) {
        float x = xs[m], y = ys[m], z = zs[m];
        float r2 = fmaf(x, x, fmaf(y, y, z * z));
        r2 = fmaxf(r2, 1e-20f);
        float rinv = rsqa(r2);
        float d = r2 * rinv;               // d = sqrt(r2), rinv = 1/d

        float s  = fmaxf(ti[m].y + tj[m].y, 1e-10f);
        float ds = d * s;
        float ea = ex2a(p.ga * ds);
        float eb = ex2a(p.gb * ds);
        float ec = ex2a(p.gc * ds);
        float phi = fmaf(p.ca, ea, fmaf(p.cb, eb, fmaf(p.cc, ec, p.cbase)));

        float xq = 5.0f - d;
        float poly = fmaf(fmaf(6.0f, xq, -15.0f), xq, 10.0f) * (xq * xq * xq);
        float sw = (d < 4.0f) ? 1.0f : ((d < 5.0f) ? poly : 0.0f);

        vs[m] = 0.5f * ti[m].x * tj[m].x * phi * sw * bs[m] * rinv;
    }

    // ---- thread-local merge over sorted keys ----
    float acc = vs[0];
    int   key = ks[0];
    #pragma unroll
    for (int m = 1; m < PPT; m++) {
        if (ks[m] == key) {
            acc += vs[m];
        } else {
            if (acc != 0.0f) atomicAdd(&out[key], acc);
            key = ks[m];
            acc = vs[m];
        }
    }

    // ---- warp segmented suffix-sum by key (keys non-decreasing by lane) ----
    float v = acc;
    int   k = key;
    #pragma unroll
    for (int off = 1; off < 32; off <<= 1) {
        int   kn = __shfl_down_sync(0xFFFFFFFFu, k, off);
        float vn = __shfl_down_sync(0xFFFFFFFFu, v, off);
        if (lane + off < 32 && kn == k) v += vn;
    }
    int kprev = __shfl_up_sync(0xFFFFFFFFu, k, 1);
    bool head = (lane == 0) || (kprev != k);
    if (head && v != 0.0f) atomicAdd(&out[k], v);
}

extern "C" void kernel_launch(void* const* d_in, const int* in_sizes, int n_in,
                              void* d_out, int out_size)
{
    const float* Z     = (const float*)d_in[0];
    const float* disp  = (const float*)d_in[1];
    const int*   idx_i = (const int*)d_in[2];
    const int*   idx_j = (const int*)d_in[3];
    const float* amask = (const float*)d_in[4];
    const float* bmask = (const float*)d_in[6];
    const float* acoef = (const float*)d_in[n_in - 4];
    const float* aexp  = (const float*)d_in[n_in - 3];
    const float* pc    = (const float*)d_in[n_in - 2];
    const float* pe    = (const float*)d_in[n_in - 1];
    float* out = (float*)d_out;

    (void)in_sizes; (void)out_size;

    prep_kernel<<<800, 128>>>(Z, amask, acoef, aexp, pc, pe, out);

    int nthreads = N_PAIRS / PPT;                 // 1.6M, divides evenly
    pair_kernel<<<nthreads / TPB, TPB>>>(
        (const float4*)disp, (const int4*)idx_i, (const int4*)idx_j,
        (const float4*)bmask, out);
}

// round 6
// speedup vs baseline: 1.1949x; 1.0471x over previous
#include <cuda_runtime.h>
#include <cuda_bf16.h>

#define N_ATOMS 100000
#define N_PAIRS 6400000
#define LOG2E 1.4426950408889634f

struct ZParams {
    float cbase;            // softmax coeff of the min-exponent term
    float ca, cb, cc;       // softmax coeffs of the other three terms
    float ga, gb, gc;       // -(e_k - e_min)*log2(e)/|a_coef|
};
__device__ ZParams g_params;
__device__ float2 g_tbl_i[N_ATOMS];   // {Z*atom_mask, Z^|a_exp|}
__device__ float2 g_tbl_j[N_ATOMS];   // {Z,           Z^|a_exp|}

__device__ __forceinline__ float ex2a(float x) {
    float r; asm("ex2.approx.f32 %0, %1;" : "=f"(r) : "f"(x)); return r;
}
__device__ __forceinline__ float lg2a(float x) {
    float r; asm("lg2.approx.f32 %0, %1;" : "=f"(r) : "f"(x)); return r;
}
__device__ __forceinline__ float rsqa(float x) {
    float r; asm("rsqrt.approx.f32 %0, %1;" : "=f"(r) : "f"(x)); return r;
}

__global__ void prep_kernel(const float* __restrict__ Z,
                            const float* __restrict__ amask,
                            const float* __restrict__ a_coef,
                            const float* __restrict__ a_exp,
                            const float* __restrict__ pc,
                            const float* __restrict__ pe,
                            float* __restrict__ out)
{
    int tid = blockIdx.x * blockDim.x + threadIdx.x;
    float aexp = fabsf(a_exp[0]);
    for (int i = tid; i < N_ATOMS; i += gridDim.x * blockDim.x) {
        float z = Z[i];
        float za = ex2a(aexp * lg2a(z));   // z^aexp, z in [1,94] > 0
        g_tbl_i[i] = make_float2(z * amask[i], za);
        g_tbl_j[i] = make_float2(z, za);
        out[i] = 0.0f;
    }
    if (tid == 0) {
        float c[4], e[4];
        float m = -1e30f;
        #pragma unroll
        for (int k = 0; k < 4; k++) {
            c[k] = fabsf(pc[k]);
            e[k] = fabsf(pe[k]);
            if (c[k] > m) m = c[k];
        }
        float sum = 0.0f, w[4];
        #pragma unroll
        for (int k = 0; k < 4; k++) { w[k] = expf(c[k] - m); sum += w[k]; }
        #pragma unroll
        for (int k = 0; k < 4; k++) w[k] /= sum;
        int kmin = 0;
        #pragma unroll
        for (int k = 1; k < 4; k++) if (e[k] < e[kmin]) kmin = k;
        float acoef = fabsf(a_coef[0]);
        float scale = -LOG2E / acoef;
        ZParams p;
        p.cbase = w[kmin];
        float* cs = &p.ca;
        float* gs = &p.ga;
        int n = 0;
        for (int k = 0; k < 4; k++) {
            if (k == kmin) continue;
            cs[n] = w[k];
            gs[n] = (e[k] - e[kmin]) * scale;
            n++;
        }
        g_params = p;
    }
}

#define PPT 4
#define TPB 256

__global__ void __launch_bounds__(TPB, 8) pair_kernel(
    const float4* __restrict__ disp4,
    const int4*   __restrict__ ii4,
    const int4*   __restrict__ jj4,
    const float4* __restrict__ bm4,
    float*        __restrict__ out)
{
    const int t = blockIdx.x * TPB + threadIdx.x;   // grid sized exactly
    const unsigned lane = threadIdx.x & 31u;

    // ---- index loads first; then long-latency random j-gathers ----
    int4 jj = __ldcs(jj4 + t);
    int4 ii = __ldcs(ii4 + t);

    int js[PPT] = {jj.x, jj.y, jj.z, jj.w};
    int ks[PPT] = {ii.x, ii.y, ii.z, ii.w};

    float2 tj[PPT];
    #pragma unroll
    for (int m = 0; m < PPT; m++) tj[m] = g_tbl_j[js[m]];

    float2 ti[PPT];
    #pragma unroll
    for (int m = 0; m < PPT; m++) ti[m] = g_tbl_i[ks[m]];

    // ---- streaming loads (evict-first, L1 reserved for tables) ----
    float4 d0 = __ldcs(disp4 + 3 * t + 0);
    float4 d1 = __ldcs(disp4 + 3 * t + 1);
    float4 d2 = __ldcs(disp4 + 3 * t + 2);
    float4 bm = __ldcs(bm4 + t);

    ZParams p = g_params;

    float xs[PPT] = {d0.x, d0.w, d1.z, d2.y};
    float ys[PPT] = {d0.y, d1.x, d1.w, d2.z};
    float zs[PPT] = {d0.z, d1.y, d2.x, d2.w};
    float bs[PPT] = {bm.x, bm.y, bm.z, bm.w};

    // ---- compute + fused merge over sorted keys ----
    float acc = 0.0f;
    int   key = ks[0];
    #pragma unroll
    for (int m = 0; m < PPT; m++) {
        float x = xs[m], y = ys[m], z = zs[m];
        float r2 = fmaf(x, x, fmaf(y, y, z * z));
        r2 = fmaxf(r2, 1e-20f);
        float rinv = rsqa(r2);
        float d = r2 * rinv;               // d = sqrt(r2), rinv = 1/d

        float s  = fmaxf(ti[m].y + tj[m].y, 1e-10f);
        float ds = d * s;
        float ea = ex2a(p.ga * ds);
        float eb = ex2a(p.gb * ds);
        float ec = ex2a(p.gc * ds);
        float phi = fmaf(p.ca, ea, fmaf(p.cb, eb, fmaf(p.cc, ec, p.cbase)));

        float xq = 5.0f - d;
        float poly = fmaf(fmaf(6.0f, xq, -15.0f), xq, 10.0f) * (xq * xq * xq);
        float sw = (d < 4.0f) ? 1.0f : ((d < 5.0f) ? poly : 0.0f);

        float v = 0.5f * ti[m].x * tj[m].x * phi * sw * bs[m] * rinv;

        if (m == 0) {
            acc = v;
        } else if (ks[m] == key) {
            acc += v;
        } else {
            if (acc != 0.0f) atomicAdd(&out[key], acc);
            key = ks[m];
            acc = v;
        }
    }

    // ---- warp segmented suffix-sum by key (keys non-decreasing by lane) ----
    float v = acc;
    int   k = key;
    #pragma unroll
    for (int off = 1; off < 32; off <<= 1) {
        int   kn = __shfl_down_sync(0xFFFFFFFFu, k, off);
        float vn = __shfl_down_sync(0xFFFFFFFFu, v, off);
        if (lane + off < 32 && kn == k) v += vn;
    }
    int kprev = __shfl_up_sync(0xFFFFFFFFu, k, 1);
    bool head = (lane == 0) || (kprev != k);
    if (head && v != 0.0f) atomicAdd(&out[k], v);
}

extern "C" void kernel_launch(void* const* d_in, const int* in_sizes, int n_in,
                              void* d_out, int out_size)
{
    const float* Z     = (const float*)d_in[0];
    const float* disp  = (const float*)d_in[1];
    const int*   idx_i = (const int*)d_in[2];
    const int*   idx_j = (const int*)d_in[3];
    const float* amask = (const float*)d_in[4];
    const float* bmask = (const float*)d_in[6];
    const float* acoef = (const float*)d_in[n_in - 4];
    const float* aexp  = (const float*)d_in[n_in - 3];
    const float* pc    = (const float*)d_in[n_in - 2];
    const float* pe    = (const float*)d_in[n_in - 1];
    float* out = (float*)d_out;

    (void)in_sizes; (void)out_size;

    prep_kernel<<<800, 128>>>(Z, amask, acoef, aexp, pc, pe, out);

    int nthreads = N_PAIRS / PPT;                 // 1.6M, divides evenly
    pair_kernel<<<nthreads / TPB, TPB>>>(
        (const float4*)disp, (const int4*)idx_i, (const int4*)idx_j,
        (const float4*)bmask, out);
}

// round 9
// speedup vs baseline: 1.1984x; 1.0029x over previous
#include <cuda_runtime.h>
#include <cuda_bf16.h>

#define N_ATOMS 100000
#define N_PAIRS 6400000
#define LOG2E 1.4426950408889634f

struct ZParams {
    float cbase;            // softmax coeff of the min-exponent term
    float ca, cb, cc;       // softmax coeffs of the other three terms
    float ga, gb, gc;       // -(e_k - e_min)*log2(e)/|a_coef|
};
__device__ ZParams g_params;
__device__ float2 g_tbl_i[N_ATOMS];   // {Z*atom_mask, Z^|a_exp|}
__device__ float2 g_tbl_j[N_ATOMS];   // {Z,           Z^|a_exp|}

__device__ __forceinline__ float ex2a(float x) {
    float r; asm("ex2.approx.f32 %0, %1;" : "=f"(r) : "f"(x)); return r;
}
__device__ __forceinline__ float lg2a(float x) {
    float r; asm("lg2.approx.f32 %0, %1;" : "=f"(r) : "f"(x)); return r;
}
__device__ __forceinline__ float rsqa(float x) {
    float r; asm("rsqrt.approx.f32 %0, %1;" : "=f"(r) : "f"(x)); return r;
}

__global__ void prep_kernel(const float* __restrict__ Z,
                            const float* __restrict__ amask,
                            const float* __restrict__ a_coef,
                            const float* __restrict__ a_exp,
                            const float* __restrict__ pc,
                            const float* __restrict__ pe,
                            float* __restrict__ out)
{
    int tid = blockIdx.x * blockDim.x + threadIdx.x;
    float aexp = fabsf(a_exp[0]);
    for (int i = tid; i < N_ATOMS; i += gridDim.x * blockDim.x) {
        float z = Z[i];
        float za = ex2a(aexp * lg2a(z));   // z^aexp, z in [1,94] > 0
        g_tbl_i[i] = make_float2(z * amask[i], za);
        g_tbl_j[i] = make_float2(z, za);
        out[i] = 0.0f;
    }
    if (tid == 0) {
        float c[4], e[4];
        float m = -1e30f;
        #pragma unroll
        for (int k = 0; k < 4; k++) {
            c[k] = fabsf(pc[k]);
            e[k] = fabsf(pe[k]);
            if (c[k] > m) m = c[k];
        }
        float sum = 0.0f, w[4];
        #pragma unroll
        for (int k = 0; k < 4; k++) { w[k] = expf(c[k] - m); sum += w[k]; }
        #pragma unroll
        for (int k = 0; k < 4; k++) w[k] /= sum;
        int kmin = 0;
        #pragma unroll
        for (int k = 1; k < 4; k++) if (e[k] < e[kmin]) kmin = k;
        float acoef = fabsf(a_coef[0]);
        float scale = -LOG2E / acoef;
        ZParams p;
        p.cbase = w[kmin];
        float* cs = &p.ca;
        float* gs = &p.ga;
        int n = 0;
        for (int k = 0; k < 4; k++) {
            if (k == kmin) continue;
            cs[n] = w[k];
            gs[n] = (e[k] - e[kmin]) * scale;
            n++;
        }
        g_params = p;
    }
}

#define PPT 2
#define TPB 256

__global__ void __launch_bounds__(TPB, 8) pair_kernel(
    const float2* __restrict__ disp2,
    const int2*   __restrict__ ii2,
    const int2*   __restrict__ jj2,
    const float2* __restrict__ bm2,
    float*        __restrict__ out)
{
    const int t = blockIdx.x * TPB + threadIdx.x;   // grid sized exactly
    const unsigned lane = threadIdx.x & 31u;

    // ---- index loads, then long-latency random j-gathers ----
    int2 jj = __ldcs(jj2 + t);
    int2 ii = __ldcs(ii2 + t);

    float2 tj0 = g_tbl_j[jj.x];
    float2 tj1 = g_tbl_j[jj.y];
    float2 ti0 = g_tbl_i[ii.x];
    float2 ti1 = g_tbl_i[ii.y];

    // ---- streaming loads (evict-first, L1 reserved for tables) ----
    float2 da = __ldcs(disp2 + 3 * t + 0);
    float2 db = __ldcs(disp2 + 3 * t + 1);
    float2 dc = __ldcs(disp2 + 3 * t + 2);
    float2 bm = __ldcs(bm2 + t);

    ZParams p = g_params;

    float xs[PPT] = {da.x, db.y};
    float ys[PPT] = {da.y, dc.x};
    float zs[PPT] = {db.x, dc.y};
    float bs[PPT] = {bm.x, bm.y};
    float2 ti[PPT] = {ti0, ti1};
    float2 tj[PPT] = {tj0, tj1};

    float vs[PPT];
    #pragma unroll
    for (int m = 0; m < PPT; m++) {
        float x = xs[m], y = ys[m], z = zs[m];
        float r2 = fmaf(x, x, fmaf(y, y, z * z));
        r2 = fmaxf(r2, 1e-20f);
        float rinv = rsqa(r2);
        float d = r2 * rinv;               // d = sqrt(r2), rinv = 1/d

        float s  = fmaxf(ti[m].y + tj[m].y, 1e-10f);
        float ds = d * s;
        float ea = ex2a(p.ga * ds);
        float eb = ex2a(p.gb * ds);
        float ec = ex2a(p.gc * ds);
        float phi = fmaf(p.ca, ea, fmaf(p.cb, eb, fmaf(p.cc, ec, p.cbase)));

        float xq = 5.0f - d;
        float poly = fmaf(fmaf(6.0f, xq, -15.0f), xq, 10.0f) * (xq * xq * xq);
        float sw = (d < 4.0f) ? 1.0f : ((d < 5.0f) ? poly : 0.0f);

        vs[m] = 0.5f * ti[m].x * tj[m].x * phi * sw * bs[m] * rinv;
    }

    // ---- merge the two pairs if same key, else flush the first ----
    float acc;
    int   key;
    if (ii.x == ii.y) {
        acc = vs[0] + vs[1];
        key = ii.x;
    } else {
        if (vs[0] != 0.0f) atomicAdd(&out[ii.x], vs[0]);
        acc = vs[1];
        key = ii.y;
    }

    // ---- warp segmented suffix-sum by key (keys non-decreasing by lane) ----
    float v = acc;
    int   k = key;
    #pragma unroll
    for (int off = 1; off < 32; off <<= 1) {
        int   kn = __shfl_down_sync(0xFFFFFFFFu, k, off);
        float vn = __shfl_down_sync(0xFFFFFFFFu, v, off);
        if (lane + off < 32 && kn == k) v += vn;
    }
    int kprev = __shfl_up_sync(0xFFFFFFFFu, k, 1);
    bool head = (lane == 0) || (kprev != k);
    if (head && v != 0.0f) atomicAdd(&out[k], v);
}

extern "C" void kernel_launch(void* const* d_in, const int* in_sizes, int n_in,
                              void* d_out, int out_size)
{
    const float* Z     = (const float*)d_in[0];
    const float* disp  = (const float*)d_in[1];
    const int*   idx_i = (const int*)d_in[2];
    const int*   idx_j = (const int*)d_in[3];
    const float* amask = (const float*)d_in[4];
    const float* bmask = (const float*)d_in[6];
    const float* acoef = (const float*)d_in[n_in - 4];
    const float* aexp  = (const float*)d_in[n_in - 3];
    const float* pc    = (const float*)d_in[n_in - 2];
    const float* pe    = (const float*)d_in[n_in - 1];
    float* out = (float*)d_out;

    (void)in_sizes; (void)out_size;

    prep_kernel<<<800, 128>>>(Z, amask, acoef, aexp, pc, pe, out);

    int nthreads = N_PAIRS / PPT;                 // 3.2M, divides evenly
    pair_kernel<<<nthreads / TPB, TPB>>>(
        (const float2*)disp, (const int2*)idx_i, (const int2*)idx_j,
        (const float2*)bmask, out);
}